// round 15
// baseline (speedup 1.0000x reference)
#include <cuda_runtime.h>
#include <cuda_fp16.h>
#include <cstdint>

// ============================================================================
// y[16384,4096] = x[16384,4096] @ W^T + bias, clamp to +-65176.48
// Harness dtypes: fp16 tensors arrive as float32.
//   d_in[0] x: f32 (16384,4096)   d_in[1] qweight: i32 (4,4096,128)
//   d_in[2] lut: f32 (4096,16)    d_in[3] bias: f32 (4096)
//   d_out y: f32 (16384,4096)
// Family-baseline ISA only (sm_103): cp.async + ldmatrix + mma.sync + mbarrier.
// R15: persistent CTAs (grid=148); the mbarrier ring runs continuously across
// tile boundaries so prologue/epilogue of consecutive tiles overlap with the
// pipeline instead of draining it (was ~13 drains/SM at 1 CTA/SM).
// ============================================================================

#define O_DIM 4096
#define I_DIM 4096
#define M_TOTAL 16384

#define BM 128
#define BN 256
#define BK 64
#define STAGES 4
#define KCHUNKS 64                   // per tile
#define THREADS 256                  // 8 warps: 2(m) x 4(n), warp tile 64x64
#define NWARPS 8

#define ROW_BYTES 128                // BK halfs, XOR-swizzled (no padding)
#define A_STAGE_BYTES (BM * ROW_BYTES)                // 16384
#define B_STAGE_BYTES (BN * ROW_BYTES)                // 32768
#define STAGE_BYTES (A_STAGE_BYTES + B_STAGE_BYTES)   // 49152
#define SMEM_BYTES (STAGES * STAGE_BYTES)             // 196608

#define N_TILES (O_DIM / BN)           // 16
#define M_TILES (M_TOTAL / BM)         // 128
#define TOTAL_TILES (N_TILES * M_TILES)  // 2048
#define GRID_P 148                     // persistent: one CTA per SM

#define DQ_BLOCKS 512
#define CVT_BLOCKS ((M_TOTAL * I_DIM) / (256 * 8))   // 32768
#define PREP_BLOCKS (DQ_BLOCKS + CVT_BLOCKS)

static constexpr float CLAMP_V = 65176.48f;  // finfo(fp16).max * 0.995

__device__ __align__(1024) __half g_weight[(size_t)O_DIM * I_DIM];
__device__ __align__(1024) __half g_x[(size_t)M_TOTAL * I_DIM];

// ============================================================================
// helpers (sm_80-level PTX only)
// ============================================================================
__device__ __forceinline__ uint32_t smem_u32(const void* p) {
    uint32_t a;
    asm("{ .reg .u64 t; cvta.to.shared.u64 t, %1; cvt.u32.u64 %0, t; }"
        : "=r"(a) : "l"(p));
    return a;
}

__device__ __forceinline__ void cp_async16(uint32_t dst, const void* src) {
    asm volatile("cp.async.cg.shared.global [%0], [%1], 16;"
                 :: "r"(dst), "l"(src));
}

// mbarrier (sm_80 baseline)
#define MBAR_INIT(addr, cnt) \
    asm volatile("mbarrier.init.shared.b64 [%0], %1;" :: "r"(addr), "r"(cnt) : "memory")
#define MBAR_ARRIVE(addr) \
    asm volatile("mbarrier.arrive.shared.b64 _, [%0];" :: "r"(addr) : "memory")
// .noinc is load-bearing: plain arrive increments expected-count first (net
// zero progress -> deadlock). .noinc counts against the init count.
#define CPASYNC_MBAR_ARRIVE(addr) \
    asm volatile("cp.async.mbarrier.arrive.noinc.shared.b64 [%0];" :: "r"(addr) : "memory")

__device__ __forceinline__ void mbar_wait(uint32_t mbar, uint32_t parity) {
    uint32_t done;
    asm volatile(
        "{\n\t.reg .pred p;\n\t"
        "mbarrier.try_wait.parity.shared.b64 p, [%1], %2;\n\t"
        "selp.b32 %0, 1, 0, p;\n\t}"
        : "=r"(done) : "r"(mbar), "r"(parity) : "memory");
    if (!done) {
        asm volatile(
            "{\n\t.reg .pred P1;\n\t"
            "W_%=:\n\t"
            "mbarrier.try_wait.parity.shared.b64 P1, [%0], %1;\n\t"
            "@P1 bra.uni D_%=;\n\t"
            "bra.uni W_%=;\n\t"
            "D_%=:\n\t}"
            :: "r"(mbar), "r"(parity) : "memory");
    }
}

__device__ __forceinline__ void ldmatrix_x4(uint32_t* r, uint32_t addr) {
    asm volatile("ldmatrix.sync.aligned.m8n8.x4.shared.b16 {%0,%1,%2,%3}, [%4];"
                 : "=r"(r[0]), "=r"(r[1]), "=r"(r[2]), "=r"(r[3]) : "r"(addr));
}

__device__ __forceinline__ void mma16816(float* c, const uint32_t* a,
                                         uint32_t b0, uint32_t b1) {
    asm volatile(
        "mma.sync.aligned.m16n8k16.row.col.f32.f16.f16.f32 "
        "{%0,%1,%2,%3}, {%4,%5,%6,%7}, {%8,%9}, {%0,%1,%2,%3};"
        : "+f"(c[0]), "+f"(c[1]), "+f"(c[2]), "+f"(c[3])
        : "r"(a[0]), "r"(a[1]), "r"(a[2]), "r"(a[3]), "r"(b0), "r"(b1));
}

// ============================================================================
// Kernel 1 (prep): blocks [0,512) dequant bitplanes; rest convert x -> fp16
// ============================================================================
__global__ void __launch_bounds__(256) prep_kernel(
    const int* __restrict__ qw, const float* __restrict__ lut,
    const float* __restrict__ x) {
    if (blockIdx.x < DQ_BLOCKS) {
        const int lane = threadIdx.x & 31;
        const int o = blockIdx.x * 8 + (threadIdx.x >> 5);

        const uint32_t lv =
            (uint32_t)__half_as_ushort(__float2half_rn(lut[o * 16 + (lane & 15)]));

        const int* q0 = qw + 0 * O_DIM * 128 + o * 128;
        const int* q1 = qw + 1 * O_DIM * 128 + o * 128;
        const int* q2 = qw + 2 * O_DIM * 128 + o * 128;
        const int* q3 = qw + 3 * O_DIM * 128 + o * 128;
        __half* wrow = g_weight + (size_t)o * I_DIM;

        #pragma unroll
        for (int it = 0; it < 4; it++) {
            const int g = it * 32 + lane;
            const uint32_t p0 = (uint32_t)q0[g];   // MSB plane
            const uint32_t p1 = (uint32_t)q1[g];
            const uint32_t p2 = (uint32_t)q2[g];
            const uint32_t p3 = (uint32_t)q3[g];   // LSB plane
            uint32_t packed[16];
            #pragma unroll
            for (int i = 0; i < 32; i += 2) {
                uint32_t c0 = (((p0 >> i) & 1u) << 3) | (((p1 >> i) & 1u) << 2) |
                              (((p2 >> i) & 1u) << 1) | ((p3 >> i) & 1u);
                uint32_t c1 = (((p0 >> (i + 1)) & 1u) << 3) |
                              (((p1 >> (i + 1)) & 1u) << 2) |
                              (((p2 >> (i + 1)) & 1u) << 1) |
                              ((p3 >> (i + 1)) & 1u);
                uint32_t w0 = __shfl_sync(0xFFFFFFFFu, lv, (int)c0);
                uint32_t w1 = __shfl_sync(0xFFFFFFFFu, lv, (int)c1);
                packed[i >> 1] = (w0 & 0xFFFFu) | (w1 << 16);
            }
            uint4* dst = reinterpret_cast<uint4*>(wrow + g * 32);
            dst[0] = make_uint4(packed[0],  packed[1],  packed[2],  packed[3]);
            dst[1] = make_uint4(packed[4],  packed[5],  packed[6],  packed[7]);
            dst[2] = make_uint4(packed[8],  packed[9],  packed[10], packed[11]);
            dst[3] = make_uint4(packed[12], packed[13], packed[14], packed[15]);
        }
    } else {
        const size_t i =
            ((size_t)(blockIdx.x - DQ_BLOCKS) * 256 + threadIdx.x) * 8;
        const float4 v0 = *reinterpret_cast<const float4*>(x + i);
        const float4 v1 = *reinterpret_cast<const float4*>(x + i + 4);
        __half2 h[4];
        h[0] = __floats2half2_rn(v0.x, v0.y);
        h[1] = __floats2half2_rn(v0.z, v0.w);
        h[2] = __floats2half2_rn(v1.x, v1.y);
        h[3] = __floats2half2_rn(v1.z, v1.w);
        *reinterpret_cast<uint4*>(g_x + i) = *reinterpret_cast<const uint4*>(h);
    }
}

// ============================================================================
// Kernel 2: persistent HMMA GEMM. 148 CTAs, each walks ~14 tiles (128x256).
// 4-stage mbarrier ring indexed by a GLOBAL chunk counter that never resets,
// so tile transitions keep the pipeline primed: producer loads tile t+1's
// chunks while consumer finishes tile t MMAs + epilogue.
// ============================================================================
__global__ void __launch_bounds__(THREADS, 1) gemm_kernel(
    const float* __restrict__ bias, float* __restrict__ out) {
    extern __shared__ __align__(1024) char smem[];
    __shared__ __align__(8) uint64_t s_mb[2 * STAGES];   // full[4], free[4]
    const uint32_t sbase = smem_u32(smem);
    const uint32_t mb_full = smem_u32(&s_mb[0]);
    const uint32_t mb_free = mb_full + STAGES * 8;

    const int tid = threadIdx.x;
    const int lane = tid & 31;
    const int warp = tid >> 5;
    const int wm = warp >> 2;            // 0..1
    const int wn = warp & 3;             // 0..3
    const uint32_t kx = (uint32_t)((warp & 4) >> 1);   // kstep stagger: 0 or 2

    if (tid == 0) {
        #pragma unroll
        for (int s = 0; s < STAGES; s++) {
            MBAR_INIT(mb_full + s * 8, THREADS);   // 256 async arrivals
            MBAR_INIT(mb_free + s * 8, NWARPS);    // 8 elected arrivals
        }
    }
    __syncthreads();    // the only full barrier in the kernel

    const int bx = blockIdx.x;
    const uint32_t n_my = (uint32_t)((TOTAL_TILES - bx + GRID_P - 1) / GRID_P);
    const uint32_t totc = n_my * KCHUNKS;     // my total chunk count

    // tile -> pointers (block swizzle: 8 m-tiles x 16 n-tiles per super-row)
#define TILE_PTRS(g, A, W, MB, NB) do {                                       \
        const int nt_ = (g) & (N_TILES - 1);                                  \
        const int mt_ = (((g) >> 7) << 3) | (((g) >> 4) & 7);                 \
        MB = mt_ * BM;  NB = nt_ * BN;                                        \
        A = g_x + (size_t)MB * I_DIM;                                         \
        W = g_weight + (size_t)NB * I_DIM;                                    \
    } while (0)

    const __half *A0, *W0, *A1, *W1;
    int mB0, nB0, mB1, nB1;
    TILE_PTRS(bx, A0, W0, mB0, nB0);
    A1 = A0; W1 = W0; mB1 = mB0; nB1 = nB0;
    if (bx + GRID_P < TOTAL_TILES) TILE_PTRS(bx + GRID_P, A1, W1, mB1, nB1);

    // ---- ldmatrix per-lane constants ----
    const uint32_t rxor = (uint32_t)(lane & 7);
    uint32_t a_row_off[4], b_row_off[4];
    #pragma unroll
    for (int i = 0; i < 4; i++)
        a_row_off[i] = (uint32_t)((wm * 64 + i * 16 + (lane & 15)) * ROW_BYTES);
    #pragma unroll
    for (int jj = 0; jj < 4; jj++)
        b_row_off[jj] = (uint32_t)((wn * 64 + jj * 16 + (lane & 7) +
                                    ((lane >> 4) << 3)) * ROW_BYTES);
    const uint32_t a_ku = (uint32_t)(lane >> 4);
    const uint32_t b_ku = (uint32_t)((lane >> 3) & 1);

#define LOAD_STAGE_PTR(stage, pA, pW, kofs) do {                              \
        const uint32_t p_a = sbase + (uint32_t)(stage) * STAGE_BYTES;         \
        const uint32_t p_b = p_a + A_STAGE_BYTES;                             \
        _Pragma("unroll")                                                     \
        for (int t = 0; t < 4; t++) {                                         \
            const int id = tid + t * 256;                                     \
            const int row = id >> 3, unit = id & 7;                           \
            cp_async16(p_a + row * ROW_BYTES + ((unit ^ (row & 7)) << 4),     \
                       (pA) + (size_t)row * I_DIM + (kofs) + unit * 8);       \
        }                                                                     \
        _Pragma("unroll")                                                     \
        for (int t = 0; t < 8; t++) {                                         \
            const int id = tid + t * 256;                                     \
            const int row = id >> 3, unit = id & 7;                           \
            cp_async16(p_b + row * ROW_BYTES + ((unit ^ (row & 7)) << 4),     \
                       (pW) + (size_t)row * I_DIM + (kofs) + unit * 8);       \
        }                                                                     \
    } while (0)

// sk is the code-position kstep; actual k offset is sk^kx (warp-group stagger)
#define LOAD_FRAGS(buf, s_a, s_b, sk) do {                                    \
        const uint32_t eff = (uint32_t)(sk) ^ kx;                             \
        const uint32_t au = ((eff * 2 + a_ku) ^ rxor) << 4;                   \
        const uint32_t bu = ((eff * 2 + b_ku) ^ rxor) << 4;                   \
        _Pragma("unroll")                                                     \
        for (int i = 0; i < 4; i++)                                           \
            ldmatrix_x4(a_regs[buf][i], (s_a) + a_row_off[i] + au);           \
        _Pragma("unroll")                                                     \
        for (int jj = 0; jj < 4; jj++)                                        \
            ldmatrix_x4(b_regs[buf][jj], (s_b) + b_row_off[jj] + bu);         \
    } while (0)

#define MMA_STEP(buf) do {                                                    \
        _Pragma("unroll")                                                     \
        for (int i = 0; i < 4; i++)                                           \
            _Pragma("unroll")                                                 \
            for (int j = 0; j < 8; j++)                                       \
                mma16816(acc[i][j], a_regs[buf][i],                           \
                         b_regs[buf][j >> 1][(j & 1) * 2],                    \
                         b_regs[buf][j >> 1][(j & 1) * 2 + 1]);               \
    } while (0)

    // prologue: first tile's chunks 0..2 in flight
    #pragma unroll
    for (int s = 0; s < STAGES - 1; s++) {
        LOAD_STAGE_PTR(s, A0, W0, s * BK);
        CPASYNC_MBAR_ARRIVE(mb_full + s * 8);
    }

    float acc[4][8][4];
    uint32_t a_regs[2][4][4], b_regs[2][4][4];

    // preload chunk 0, kstep-position 0 into buf 0
    mbar_wait(mb_full + 0, 0u);
    LOAD_FRAGS(0, sbase, sbase + A_STAGE_BYTES, 0);

    uint32_t c = 0;                       // GLOBAL consumer chunk counter
    int g = bx;
    while (g < TOTAL_TILES) {
        #pragma unroll
        for (int i = 0; i < 4; i++)
            #pragma unroll
            for (int j = 0; j < 8; j++)
                #pragma unroll
                for (int q = 0; q < 4; q++) acc[i][j][q] = 0.0f;

        #pragma unroll 2
        for (int it = 0; it < KCHUNKS; it++, c++) {
            const int s = (int)(c & (STAGES - 1));
            const uint32_t s_a = sbase + (uint32_t)s * STAGE_BYTES;
            const uint32_t s_b = s_a + A_STAGE_BYTES;

            // buf0 holds (c, pos0) fragments — compute immediately
            LOAD_FRAGS(1, s_a, s_b, 1);
            MMA_STEP(0);

            // producer: chunk c+3 (may belong to the NEXT tile: it >= 61)
            if (c + 3 < totc) {
                const int s3 = (int)((c + 3) & (STAGES - 1));
                if (c + 3 >= STAGES)
                    mbar_wait(mb_free + s3 * 8,
                              (uint32_t)(((c + 3 - STAGES) >> 2) & 1));
                if (it < KCHUNKS - 3) {
                    LOAD_STAGE_PTR(s3, A0, W0, (it + 3) * BK);
                } else {
                    LOAD_STAGE_PTR(s3, A1, W1, (it + 3 - KCHUNKS) * BK);
                }
                CPASYNC_MBAR_ARRIVE(mb_full + s3 * 8);
            }

            LOAD_FRAGS(0, s_a, s_b, 2);
            MMA_STEP(1);
            LOAD_FRAGS(1, s_a, s_b, 3);   // last smem reads of slot s

            // release slot s: arrive (release) orders the prior LDSMs
            if (lane == 0) MBAR_ARRIVE(mb_free + s * 8);

            MMA_STEP(0);

            // cross-chunk prefetch: (c+1, pos0) into buf0 during pos3 MMAs
            if (c + 1 < totc) {
                const int sn = (int)((c + 1) & (STAGES - 1));
                const uint32_t n_a = sbase + (uint32_t)sn * STAGE_BYTES;
                mbar_wait(mb_full + sn * 8, (uint32_t)(((c + 1) >> 2) & 1));
                LOAD_FRAGS(0, n_a, n_a + A_STAGE_BYTES, 0);
            }
            MMA_STEP(1);
        }

        // ---------------- epilogue for tile g (pipeline keeps running) ------
        {
            float2 fb[8];
            #pragma unroll
            for (int j = 0; j < 8; j++) {
                const int col = nB0 + wn * 64 + j * 8 + (lane & 3) * 2;
                fb[j] = *reinterpret_cast<const float2*>(bias + col);
            }
            #pragma unroll
            for (int i = 0; i < 4; i++) {
                const int row0 = mB0 + wm * 64 + i * 16 + (lane >> 2);
                #pragma unroll
                for (int rr = 0; rr < 2; rr++) {
                    const size_t row = (size_t)(row0 + rr * 8);
                    float* orow = out + row * O_DIM + nB0 + wn * 64 +
                                  (lane & 3) * 2;
                    #pragma unroll
                    for (int j = 0; j < 8; j++) {
                        float v0 = acc[i][j][rr * 2 + 0] + fb[j].x;
                        float v1 = acc[i][j][rr * 2 + 1] + fb[j].y;
                        v0 = fminf(fmaxf(v0, -CLAMP_V), CLAMP_V);
                        v1 = fminf(fmaxf(v1, -CLAMP_V), CLAMP_V);
                        *reinterpret_cast<float2*>(orow + j * 8) =
                            make_float2(v0, v1);
                    }
                }
            }
        }

        // rotate tile pointers
        g += GRID_P;
        A0 = A1; W0 = W1; mB0 = mB1; nB0 = nB1;
        if (g + GRID_P < TOTAL_TILES)
            TILE_PTRS(g + GRID_P, A1, W1, mB1, nB1);
    }
#undef TILE_PTRS
#undef LOAD_STAGE_PTR
#undef LOAD_FRAGS
#undef MMA_STEP
}

// ============================================================================
// Host launcher
// ============================================================================
extern "C" void kernel_launch(void* const* d_in, const int* in_sizes, int n_in,
                              void* d_out, int out_size) {
    (void)in_sizes; (void)n_in; (void)out_size;
    const float* x    = (const float*)d_in[0];
    const int*   qw   = (const int*)d_in[1];
    const float* lut  = (const float*)d_in[2];
    const float* bias = (const float*)d_in[3];
    float* out = (float*)d_out;

    prep_kernel<<<PREP_BLOCKS, 256>>>(qw, lut, x);

    cudaFuncSetAttribute(gemm_kernel, cudaFuncAttributeMaxDynamicSharedMemorySize,
                         SMEM_BYTES);
    gemm_kernel<<<GRID_P, THREADS, SMEM_BYTES>>>(bias, out);
}

// round 16
// speedup vs baseline: 1.0704x; 1.0704x over previous
#include <cuda_runtime.h>
#include <cuda_fp16.h>
#include <cstdint>

// ============================================================================
// y[16384,4096] = x[16384,4096] @ W^T + bias, clamp to +-65176.48
// Harness dtypes: fp16 tensors arrive as float32.
//   d_in[0] x: f32 (16384,4096)   d_in[1] qweight: i32 (4,4096,128)
//   d_in[2] lut: f32 (4096,16)    d_in[3] bias: f32 (4096)
//   d_out y: f32 (16384,4096)
// Family-baseline ISA only (sm_103): cp.async + ldmatrix + mma.sync + mbarrier.
// R16: persistent CTAs with IT-LOCAL slot/parity arithmetic. Because
// KCHUNKS=64 is divisible by 4 and contributes an even number of parity
// groups per tile, slot/parity are pure functions of the within-tile index:
//   slot = it&3, full-parity = (it>>2)&1, free-parity = ((it-1)>>2)&1,
//   prefetch-parity = ((it+1)>>2)&1.
// This restores R14's unroll-4 constant folding (R15's regression was the
// dynamic global-counter bookkeeping) while keeping the ring alive across
// tile boundaries (producer prefetches tile t+1 during tile t's tail+epilogue).
// ============================================================================

#define O_DIM 4096
#define I_DIM 4096
#define M_TOTAL 16384

#define BM 128
#define BN 256
#define BK 64
#define STAGES 4
#define KCHUNKS 64                   // per tile
#define THREADS 256                  // 8 warps: 2(m) x 4(n), warp tile 64x64
#define NWARPS 8

#define ROW_BYTES 128                // BK halfs, XOR-swizzled (no padding)
#define A_STAGE_BYTES (BM * ROW_BYTES)                // 16384
#define B_STAGE_BYTES (BN * ROW_BYTES)                // 32768
#define STAGE_BYTES (A_STAGE_BYTES + B_STAGE_BYTES)   // 49152
#define SMEM_BYTES (STAGES * STAGE_BYTES)             // 196608

#define N_TILES (O_DIM / BN)           // 16
#define M_TILES (M_TOTAL / BM)         // 128
#define TOTAL_TILES (N_TILES * M_TILES)  // 2048
#define GRID_P 148                     // persistent: one CTA per SM

#define DQ_BLOCKS 512
#define CVT_BLOCKS ((M_TOTAL * I_DIM) / (256 * 8))   // 32768
#define PREP_BLOCKS (DQ_BLOCKS + CVT_BLOCKS)

static constexpr float CLAMP_V = 65176.48f;  // finfo(fp16).max * 0.995

__device__ __align__(1024) __half g_weight[(size_t)O_DIM * I_DIM];
__device__ __align__(1024) __half g_x[(size_t)M_TOTAL * I_DIM];

// ============================================================================
// helpers (sm_80-level PTX only)
// ============================================================================
__device__ __forceinline__ uint32_t smem_u32(const void* p) {
    uint32_t a;
    asm("{ .reg .u64 t; cvta.to.shared.u64 t, %1; cvt.u32.u64 %0, t; }"
        : "=r"(a) : "l"(p));
    return a;
}

__device__ __forceinline__ void cp_async16(uint32_t dst, const void* src) {
    asm volatile("cp.async.cg.shared.global [%0], [%1], 16;"
                 :: "r"(dst), "l"(src));
}

// mbarrier (sm_80 baseline)
#define MBAR_INIT(addr, cnt) \
    asm volatile("mbarrier.init.shared.b64 [%0], %1;" :: "r"(addr), "r"(cnt) : "memory")
#define MBAR_ARRIVE(addr) \
    asm volatile("mbarrier.arrive.shared.b64 _, [%0];" :: "r"(addr) : "memory")
// .noinc is load-bearing: plain arrive increments expected-count first (net
// zero progress -> deadlock). .noinc counts against the init count.
#define CPASYNC_MBAR_ARRIVE(addr) \
    asm volatile("cp.async.mbarrier.arrive.noinc.shared.b64 [%0];" :: "r"(addr) : "memory")

__device__ __forceinline__ void mbar_wait(uint32_t mbar, uint32_t parity) {
    uint32_t done;
    asm volatile(
        "{\n\t.reg .pred p;\n\t"
        "mbarrier.try_wait.parity.shared.b64 p, [%1], %2;\n\t"
        "selp.b32 %0, 1, 0, p;\n\t}"
        : "=r"(done) : "r"(mbar), "r"(parity) : "memory");
    if (!done) {
        asm volatile(
            "{\n\t.reg .pred P1;\n\t"
            "W_%=:\n\t"
            "mbarrier.try_wait.parity.shared.b64 P1, [%0], %1;\n\t"
            "@P1 bra.uni D_%=;\n\t"
            "bra.uni W_%=;\n\t"
            "D_%=:\n\t}"
            :: "r"(mbar), "r"(parity) : "memory");
    }
}

__device__ __forceinline__ void ldmatrix_x4(uint32_t* r, uint32_t addr) {
    asm volatile("ldmatrix.sync.aligned.m8n8.x4.shared.b16 {%0,%1,%2,%3}, [%4];"
                 : "=r"(r[0]), "=r"(r[1]), "=r"(r[2]), "=r"(r[3]) : "r"(addr));
}

__device__ __forceinline__ void mma16816(float* c, const uint32_t* a,
                                         uint32_t b0, uint32_t b1) {
    asm volatile(
        "mma.sync.aligned.m16n8k16.row.col.f32.f16.f16.f32 "
        "{%0,%1,%2,%3}, {%4,%5,%6,%7}, {%8,%9}, {%0,%1,%2,%3};"
        : "+f"(c[0]), "+f"(c[1]), "+f"(c[2]), "+f"(c[3])
        : "r"(a[0]), "r"(a[1]), "r"(a[2]), "r"(a[3]), "r"(b0), "r"(b1));
}

// ============================================================================
// Kernel 1 (prep): blocks [0,512) dequant bitplanes; rest convert x -> fp16
// ============================================================================
__global__ void __launch_bounds__(256) prep_kernel(
    const int* __restrict__ qw, const float* __restrict__ lut,
    const float* __restrict__ x) {
    if (blockIdx.x < DQ_BLOCKS) {
        const int lane = threadIdx.x & 31;
        const int o = blockIdx.x * 8 + (threadIdx.x >> 5);

        const uint32_t lv =
            (uint32_t)__half_as_ushort(__float2half_rn(lut[o * 16 + (lane & 15)]));

        const int* q0 = qw + 0 * O_DIM * 128 + o * 128;
        const int* q1 = qw + 1 * O_DIM * 128 + o * 128;
        const int* q2 = qw + 2 * O_DIM * 128 + o * 128;
        const int* q3 = qw + 3 * O_DIM * 128 + o * 128;
        __half* wrow = g_weight + (size_t)o * I_DIM;

        #pragma unroll
        for (int it = 0; it < 4; it++) {
            const int g = it * 32 + lane;
            const uint32_t p0 = (uint32_t)q0[g];   // MSB plane
            const uint32_t p1 = (uint32_t)q1[g];
            const uint32_t p2 = (uint32_t)q2[g];
            const uint32_t p3 = (uint32_t)q3[g];   // LSB plane
            uint32_t packed[16];
            #pragma unroll
            for (int i = 0; i < 32; i += 2) {
                uint32_t c0 = (((p0 >> i) & 1u) << 3) | (((p1 >> i) & 1u) << 2) |
                              (((p2 >> i) & 1u) << 1) | ((p3 >> i) & 1u);
                uint32_t c1 = (((p0 >> (i + 1)) & 1u) << 3) |
                              (((p1 >> (i + 1)) & 1u) << 2) |
                              (((p2 >> (i + 1)) & 1u) << 1) |
                              ((p3 >> (i + 1)) & 1u);
                uint32_t w0 = __shfl_sync(0xFFFFFFFFu, lv, (int)c0);
                uint32_t w1 = __shfl_sync(0xFFFFFFFFu, lv, (int)c1);
                packed[i >> 1] = (w0 & 0xFFFFu) | (w1 << 16);
            }
            uint4* dst = reinterpret_cast<uint4*>(wrow + g * 32);
            dst[0] = make_uint4(packed[0],  packed[1],  packed[2],  packed[3]);
            dst[1] = make_uint4(packed[4],  packed[5],  packed[6],  packed[7]);
            dst[2] = make_uint4(packed[8],  packed[9],  packed[10], packed[11]);
            dst[3] = make_uint4(packed[12], packed[13], packed[14], packed[15]);
        }
    } else {
        const size_t i =
            ((size_t)(blockIdx.x - DQ_BLOCKS) * 256 + threadIdx.x) * 8;
        const float4 v0 = *reinterpret_cast<const float4*>(x + i);
        const float4 v1 = *reinterpret_cast<const float4*>(x + i + 4);
        __half2 h[4];
        h[0] = __floats2half2_rn(v0.x, v0.y);
        h[1] = __floats2half2_rn(v0.z, v0.w);
        h[2] = __floats2half2_rn(v1.x, v1.y);
        h[3] = __floats2half2_rn(v1.z, v1.w);
        *reinterpret_cast<uint4*>(g_x + i) = *reinterpret_cast<const uint4*>(h);
    }
}

// ============================================================================
// Kernel 2: persistent HMMA GEMM, it-local slot/parity (fully foldable).
// ============================================================================
__global__ void __launch_bounds__(THREADS, 1) gemm_kernel(
    const float* __restrict__ bias, float* __restrict__ out) {
    extern __shared__ __align__(1024) char smem[];
    __shared__ __align__(8) uint64_t s_mb[2 * STAGES];   // full[4], free[4]
    const uint32_t sbase = smem_u32(smem);
    const uint32_t mb_full = smem_u32(&s_mb[0]);
    const uint32_t mb_free = mb_full + STAGES * 8;

    const int tid = threadIdx.x;
    const int lane = tid & 31;
    const int warp = tid >> 5;
    const int wm = warp >> 2;            // 0..1
    const int wn = warp & 3;             // 0..3
    const uint32_t kx = (uint32_t)((warp & 4) >> 1);   // kstep stagger: 0 or 2

    if (tid == 0) {
        #pragma unroll
        for (int s = 0; s < STAGES; s++) {
            MBAR_INIT(mb_full + s * 8, THREADS);   // 256 async arrivals
            MBAR_INIT(mb_free + s * 8, NWARPS);    // 8 elected arrivals
        }
    }
    __syncthreads();    // the only full barrier in the kernel

    const int bx = blockIdx.x;

    // tile -> pointers (block swizzle: 8 m-tiles x 16 n-tiles per super-row)
#define TILE_PTRS(g, A, W, MB, NB) do {                                       \
        const int nt_ = (g) & (N_TILES - 1);                                  \
        const int mt_ = (((g) >> 7) << 3) | (((g) >> 4) & 7);                 \
        MB = mt_ * BM;  NB = nt_ * BN;                                        \
        A = g_x + (size_t)MB * I_DIM;                                         \
        W = g_weight + (size_t)NB * I_DIM;                                    \
    } while (0)

    const __half *A0, *W0, *A1, *W1;
    int mB0, nB0, mB1, nB1;
    TILE_PTRS(bx, A0, W0, mB0, nB0);
    A1 = A0; W1 = W0; mB1 = mB0; nB1 = nB0;
    if (bx + GRID_P < TOTAL_TILES) TILE_PTRS(bx + GRID_P, A1, W1, mB1, nB1);

    // ---- ldmatrix per-lane constants ----
    const uint32_t rxor = (uint32_t)(lane & 7);
    uint32_t a_row_off[4], b_row_off[4];
    #pragma unroll
    for (int i = 0; i < 4; i++)
        a_row_off[i] = (uint32_t)((wm * 64 + i * 16 + (lane & 15)) * ROW_BYTES);
    #pragma unroll
    for (int jj = 0; jj < 4; jj++)
        b_row_off[jj] = (uint32_t)((wn * 64 + jj * 16 + (lane & 7) +
                                    ((lane >> 4) << 3)) * ROW_BYTES);
    const uint32_t a_ku = (uint32_t)(lane >> 4);
    const uint32_t b_ku = (uint32_t)((lane >> 3) & 1);

#define LOAD_STAGE_PTR(stage, pA, pW, kofs) do {                              \
        const uint32_t p_a = sbase + (uint32_t)(stage) * STAGE_BYTES;         \
        const uint32_t p_b = p_a + A_STAGE_BYTES;                             \
        _Pragma("unroll")                                                     \
        for (int t = 0; t < 4; t++) {                                         \
            const int id = tid + t * 256;                                     \
            const int row = id >> 3, unit = id & 7;                           \
            cp_async16(p_a + row * ROW_BYTES + ((unit ^ (row & 7)) << 4),     \
                       (pA) + (size_t)row * I_DIM + (kofs) + unit * 8);       \
        }                                                                     \
        _Pragma("unroll")                                                     \
        for (int t = 0; t < 8; t++) {                                         \
            const int id = tid + t * 256;                                     \
            const int row = id >> 3, unit = id & 7;                           \
            cp_async16(p_b + row * ROW_BYTES + ((unit ^ (row & 7)) << 4),     \
                       (pW) + (size_t)row * I_DIM + (kofs) + unit * 8);       \
        }                                                                     \
    } while (0)

// sk is the code-position kstep; actual k offset is sk^kx (warp-group stagger)
#define LOAD_FRAGS(buf, s_a, s_b, sk) do {                                    \
        const uint32_t eff = (uint32_t)(sk) ^ kx;                             \
        const uint32_t au = ((eff * 2 + a_ku) ^ rxor) << 4;                   \
        const uint32_t bu = ((eff * 2 + b_ku) ^ rxor) << 4;                   \
        _Pragma("unroll")                                                     \
        for (int i = 0; i < 4; i++)                                           \
            ldmatrix_x4(a_regs[buf][i], (s_a) + a_row_off[i] + au);           \
        _Pragma("unroll")                                                     \
        for (int jj = 0; jj < 4; jj++)                                        \
            ldmatrix_x4(b_regs[buf][jj], (s_b) + b_row_off[jj] + bu);         \
    } while (0)

#define MMA_STEP(buf) do {                                                    \
        _Pragma("unroll")                                                     \
        for (int i = 0; i < 4; i++)                                           \
            _Pragma("unroll")                                                 \
            for (int j = 0; j < 8; j++)                                       \
                mma16816(acc[i][j], a_regs[buf][i],                           \
                         b_regs[buf][j >> 1][(j & 1) * 2],                    \
                         b_regs[buf][j >> 1][(j & 1) * 2 + 1]);               \
    } while (0)

    // prologue: first tile's chunks 0..2 in flight
    #pragma unroll
    for (int s = 0; s < STAGES - 1; s++) {
        LOAD_STAGE_PTR(s, A0, W0, s * BK);
        CPASYNC_MBAR_ARRIVE(mb_full + s * 8);
    }

    float acc[4][8][4];
    uint32_t a_regs[2][4][4], b_regs[2][4][4];

    // preload chunk 0, kstep-position 0 into buf 0
    mbar_wait(mb_full + 0, 0u);
    LOAD_FRAGS(0, sbase, sbase + A_STAGE_BYTES, 0);

    int g = bx;
    int first = 1;
    while (g < TOTAL_TILES) {
        const int has_next = (g + GRID_P < TOTAL_TILES);

        #pragma unroll
        for (int i = 0; i < 4; i++)
            #pragma unroll
            for (int j = 0; j < 8; j++)
                #pragma unroll
                for (int q = 0; q < 4; q++) acc[i][j][q] = 0.0f;

        #pragma unroll 4
        for (int it = 0; it < KCHUNKS; it++) {
            const int s = it & (STAGES - 1);          // folds under unroll 4
            const uint32_t s_a = sbase + (uint32_t)s * STAGE_BYTES;
            const uint32_t s_b = s_a + A_STAGE_BYTES;

            // buf0 holds (it, pos0) fragments — compute immediately
            LOAD_FRAGS(1, s_a, s_b, 1);
            MMA_STEP(0);

            // producer: chunk it+3 (crosses into next tile when it >= 61)
            if (it < KCHUNKS - 3 || has_next) {
                const int s3 = (it + 3) & (STAGES - 1);
                // free-parity: ((it-1)>>2)&1 — signed shift gives 1 at it==0,
                // which is correct for every tile except the very first chunk
                // of the first tile (skip: nothing ever used slot 3 yet).
                if (!(first && it == 0))
                    mbar_wait(mb_free + s3 * 8,
                              (uint32_t)(((it - 1) >> 2) & 1));
                if (it < KCHUNKS - 3) {
                    LOAD_STAGE_PTR(s3, A0, W0, (it + 3) * BK);
                } else {
                    LOAD_STAGE_PTR(s3, A1, W1, (it + 3 - KCHUNKS) * BK);
                }
                CPASYNC_MBAR_ARRIVE(mb_full + s3 * 8);
            }

            LOAD_FRAGS(0, s_a, s_b, 2);
            MMA_STEP(1);
            LOAD_FRAGS(1, s_a, s_b, 3);   // last smem reads of slot s

            // release slot s: arrive (release) orders the prior LDSMs
            if (lane == 0) MBAR_ARRIVE(mb_free + s * 8);

            MMA_STEP(0);

            // prefetch (it+1, pos0) into buf0 during pos3 MMAs; at it==63
            // this is the NEXT tile's chunk 0 (slot 0, parity 0 — continuous)
            if (it < KCHUNKS - 1 || has_next) {
                const int sn = (it + 1) & (STAGES - 1);
                const uint32_t n_a = sbase + (uint32_t)sn * STAGE_BYTES;
                mbar_wait(mb_full + sn * 8, (uint32_t)(((it + 1) >> 2) & 1));
                LOAD_FRAGS(0, n_a, n_a + A_STAGE_BYTES, 0);
            }
            MMA_STEP(1);
        }

        // ---------------- epilogue for tile g (ring keeps running) ----------
        {
            float2 fb[8];
            #pragma unroll
            for (int j = 0; j < 8; j++) {
                const int col = nB0 + wn * 64 + j * 8 + (lane & 3) * 2;
                fb[j] = *reinterpret_cast<const float2*>(bias + col);
            }
            #pragma unroll
            for (int i = 0; i < 4; i++) {
                const int row0 = mB0 + wm * 64 + i * 16 + (lane >> 2);
                #pragma unroll
                for (int rr = 0; rr < 2; rr++) {
                    const size_t row = (size_t)(row0 + rr * 8);
                    float* orow = out + row * O_DIM + nB0 + wn * 64 +
                                  (lane & 3) * 2;
                    #pragma unroll
                    for (int j = 0; j < 8; j++) {
                        float v0 = acc[i][j][rr * 2 + 0] + fb[j].x;
                        float v1 = acc[i][j][rr * 2 + 1] + fb[j].y;
                        v0 = fminf(fmaxf(v0, -CLAMP_V), CLAMP_V);
                        v1 = fminf(fmaxf(v1, -CLAMP_V), CLAMP_V);
                        *reinterpret_cast<float2*>(orow + j * 8) =
                            make_float2(v0, v1);
                    }
                }
            }
        }

        // rotate tile pointers
        g += GRID_P;
        first = 0;
        A0 = A1; W0 = W1; mB0 = mB1; nB0 = nB1;
        if (g + GRID_P < TOTAL_TILES)
            TILE_PTRS(g + GRID_P, A1, W1, mB1, nB1);
    }
#undef TILE_PTRS
#undef LOAD_STAGE_PTR
#undef LOAD_FRAGS
#undef MMA_STEP
}

// ============================================================================
// Host launcher
// ============================================================================
extern "C" void kernel_launch(void* const* d_in, const int* in_sizes, int n_in,
                              void* d_out, int out_size) {
    (void)in_sizes; (void)n_in; (void)out_size;
    const float* x    = (const float*)d_in[0];
    const int*   qw   = (const int*)d_in[1];
    const float* lut  = (const float*)d_in[2];
    const float* bias = (const float*)d_in[3];
    float* out = (float*)d_out;

    prep_kernel<<<PREP_BLOCKS, 256>>>(qw, lut, x);

    cudaFuncSetAttribute(gemm_kernel, cudaFuncAttributeMaxDynamicSharedMemorySize,
                         SMEM_BYTES);
    gemm_kernel<<<GRID_P, THREADS, SMEM_BYTES>>>(bias, out);
}